// round 1
// baseline (speedup 1.0000x reference)
#include <cuda_runtime.h>
#include <cuda_bf16.h>

#define CLASSNUM 1000
#define LGT 16
#define NROWS 4096
#define DCOLS (CLASSNUM * LGT)   // 16000

__global__ void zero_out_kernel(float* out) {
    if (threadIdx.x == 0) out[0] = 0.0f;
}

__global__ __launch_bounds__(256, 8)
void rvsml_loss_kernel(const float* __restrict__ inputs,
                       const float* __restrict__ labels,
                       float* __restrict__ out) {
    const int row = blockIdx.x;
    const int tid = threadIdx.x;

    const float4* rowp = reinterpret_cast<const float4*>(inputs + (long long)row * DCOLS);
    const int nvec = DCOLS / 4;  // 4000

    // Stream the row, accumulate sum of squares.
    float acc = 0.0f;
    #pragma unroll 4
    for (int i = tid; i < nvec; i += 256) {
        float4 v = rowp[i];
        acc = fmaf(v.x, v.x, acc);
        acc = fmaf(v.y, v.y, acc);
        acc = fmaf(v.z, v.z, acc);
        acc = fmaf(v.w, v.w, acc);
    }

    // Block reduce acc -> sq
    __shared__ float warp_sums[8];
    __shared__ float sq_sh;

    // warp reduce
    #pragma unroll
    for (int off = 16; off > 0; off >>= 1)
        acc += __shfl_xor_sync(0xFFFFFFFFu, acc, off);
    if ((tid & 31) == 0) warp_sums[tid >> 5] = acc;
    __syncthreads();

    if (tid < 32) {
        float v = (tid < 8) ? warp_sums[tid] : 0.0f;
        #pragma unroll
        for (int off = 4; off > 0; off >>= 1)
            v += __shfl_xor_sync(0xFFFFFFFFu, v, off);
        if (tid == 0) sq_sh = v;
    }
    __syncthreads();

    // Lanes 0..15 of warp 0: gather + weighted contribution
    if (tid < 32) {
        const float sq = sq_sh;
        const float* lab = labels + (long long)row * (LGT + 1);
        float contrib = 0.0f;
        if (tid < LGT) {
            const int c = (int)lab[LGT];            // class id stored as float
            const float w = lab[tid];               // weight j
            const float g = inputs[(long long)row * DCOLS + c * LGT + tid]; // L2 hit
            contrib = w * (sq + 1.0f - 2.0f * g);
        }
        // reduce over 32 lanes (upper 16 contribute 0)
        #pragma unroll
        for (int off = 16; off > 0; off >>= 1)
            contrib += __shfl_xor_sync(0xFFFFFFFFu, contrib, off);
        if (tid == 0)
            atomicAdd(out, contrib * (1.0f / (float)NROWS));
    }
}

extern "C" void kernel_launch(void* const* d_in, const int* in_sizes, int n_in,
                              void* d_out, int out_size) {
    const float* inputs = (const float*)d_in[0];
    const float* labels = (const float*)d_in[1];
    float* out = (float*)d_out;

    zero_out_kernel<<<1, 32>>>(out);
    rvsml_loss_kernel<<<NROWS, 256>>>(inputs, labels, out);
}